// round 14
// baseline (speedup 1.0000x reference)
#include <cuda_runtime.h>
#include <cuda_fp16.h>
#include <cstdint>

#define BB 32
#define CC 16
#define UU 16
#define LL 128
#define PW (LL*LL)
#define KP 5
#define MKC 80
#define MLU 80

// C is scaled by 4096 (exact power of 2); band2T pre-divided by 4096.
#define CSCALE 4096.0f

// ------------------------------- scratch ------------------------------------
__device__ float  g_band1[LL*25];      // packed band of cheb1 [p][25]
__device__ float  g_band2T[25*LL];     // packed band of cheb2 /CSCALE, [j][q]
__device__ __half g_Chi[MLU*88];       // coef*CSCALE fp16 [m][kk pad 88]

// --------------------------- helpers ------------------------------
__device__ __forceinline__ void cp16(uint32_t dst, const void* src){
  asm volatile("cp.async.cg.shared.global [%0], [%1], 16;" :: "r"(dst), "l"(src));
}
__device__ __forceinline__ void cp_commit(){ asm volatile("cp.async.commit_group;"); }
template<int N> __device__ __forceinline__ void cp_wait(){
  asm volatile("cp.async.wait_group %0;" :: "n"(N));
}
__device__ __forceinline__ uint32_t smem_u32(const void* p){
  return (uint32_t)__cvta_generic_to_shared(p);
}
// pack two floats to fp16x2 (lo arg in low half)
__device__ __forceinline__ uint32_t f2h2(float lo, float hi){
  uint32_t r;
  asm("cvt.rn.f16x2.f32 %0, %1, %2;" : "=r"(r) : "f"(hi), "f"(lo));
  return r;
}
// m16n8k16 fp16 MMA, fp32 accumulate
__device__ __forceinline__ void mma16816h(float* d, const uint32_t* a, const uint32_t* b){
  asm volatile("mma.sync.aligned.m16n8k16.row.col.f32.f16.f16.f32 "
    "{%0,%1,%2,%3}, {%4,%5,%6,%7}, {%8,%9}, {%0,%1,%2,%3};"
    : "+f"(d[0]),"+f"(d[1]),"+f"(d[2]),"+f"(d[3])
    : "r"(a[0]),"r"(a[1]),"r"(a[2]),"r"(a[3]), "r"(b[0]),"r"(b[1]));
}
__device__ __forceinline__ void ldsm4(uint32_t* r, uint32_t addr){
  asm volatile("ldmatrix.sync.aligned.m8n8.x4.shared.b16 {%0,%1,%2,%3}, [%4];"
    : "=r"(r[0]),"=r"(r[1]),"=r"(r[2]),"=r"(r[3]) : "r"(addr));
}
__device__ __forceinline__ void ldsm4t(uint32_t* r, uint32_t addr){
  asm volatile("ldmatrix.sync.aligned.m8n8.x4.trans.shared.b16 {%0,%1,%2,%3}, [%4];"
    : "=r"(r[0]),"=r"(r[1]),"=r"(r[2]),"=r"(r[3]) : "r"(addr));
}

// ============================================================================
// Prep: band tables (T_k has bandwidth k — exact structural zeros).
// band1[p][k*k+k+d] = c1[k][p+d][p];  band2T[(k*k+k+d)][q] = c2[k][q+d][q]/CSCALE
// C[m=(l,u)][kk=(k1,c)]*CSCALE -> fp16, kk padded to 88.
// ============================================================================
__global__ void prep_tabs(const float* __restrict__ c1, const float* __restrict__ c2,
                          const float* __restrict__ coefs){
  int gt = blockIdx.x*128 + threadIdx.x;   // 64 x 128 = 8192
  if (gt < LL){
    int t = gt;
#pragma unroll
    for (int k = 0; k < KP; k++)
      for (int d = -k; d <= k; d++){
        int h = t + d;
        bool ok = (h >= 0 && h < LL);
        g_band1[t*25 + k*k + k + d] = ok ? c1[(k*LL + h)*LL + t] : 0.f;
        g_band2T[(k*k + k + d)*LL + t] = ok ? (c2[(k*LL + h)*LL + t] * (1.0f/CSCALE)) : 0.f;
      }
  }
  for (int i = gt; i < MLU*88; i += 8192){
    int m = i / 88, kk = i % 88;
    float v = 0.f;
    if (kk < MKC){
      int l = m >> 4, u = m & 15, k1 = kk >> 4, c = kk & 15;
      v = coefs[((k1*KP + l)*CC + c)*UU + u] * CSCALE;
    }
    g_Chi[i] = __float2half_rn(v);
  }
}

// ============================================================================
// Fully fused kernel, one block per (b, p):
//   phase A (fp32 stencil, d-major): t1[kk][w] -> single fp16 ldsm tile
//   phase B (HMMA fp16): s[m][w] = Chi[m][kk] * t1f16[kk][w]
//   phase C (shfl-windowed stencil, 4 warps x 4u): out = sum_{l,d} band2T*s
//           s kept in FP16 (stride-136 rows, conflict-free), band2T via __ldg.
// SMEM (35968 B): t1[80][136]h | Chi[80][88]h | band1[32]f
//   phase C overlay: s[80][136]fp16 over t1 region (same 21760 B).
// ============================================================================
#define F_T1  0
#define F_CH  21760
#define F_BND1 35840
#define F_SMEM 35968           // bytes
#define F_SD  0                // s tile [80][136] fp16 overlays t1

__global__ __launch_bounds__(320,3) void fused_all(const float* __restrict__ x,
                                                   float* __restrict__ out){
  extern __shared__ char smem[];
  uint32_t sb = smem_u32(smem);
  int tid = threadIdx.x, wid = tid >> 5, lane = tid & 31;
  int p = blockIdx.x, b = blockIdx.y;

  // ---- async C-tile loads (overlap with stencil below) ----
  for (int i = tid; i < 880; i += 320){
    int r = i / 11, ch = i % 11;
    cp16(sb + F_CH + r*176 + ch*16, g_Chi + r*88 + ch*8);
  }
  cp_commit();

  // ---- band1[p] into smem (broadcast table for phase A) ----
  float* bnd_s = (float*)(smem + F_BND1);
  if (tid < 25) bnd_s[tid] = g_band1[p*25 + tid];
  __syncthreads();

  // ---- phase A: stage-1 stencil, d-major; output single fp16 tile ----
  for (int i = tid; i < 512; i += 320){
    int c  = i >> 5;
    int w4 = (i & 31) << 2;
    const float* xs = x + (size_t)(b*CC + c)*PW + w4;
    float4 acck[5];
#pragma unroll
    for (int k = 0; k < KP; k++) acck[k] = make_float4(0.f,0.f,0.f,0.f);
#pragma unroll
    for (int d = -4; d <= 4; d++){
      int h = p + d;
      h = h < 0 ? 0 : (h > 127 ? 127 : h);
      float4 v = *(const float4*)(xs + h*LL);
      int ad = d < 0 ? -d : d;
#pragma unroll
      for (int k = 0; k < KP; k++){
        if (k >= ad){
          float cf = bnd_s[k*k + k + d];
          acck[k].x = fmaf(cf, v.x, acck[k].x);
          acck[k].y = fmaf(cf, v.y, acck[k].y);
          acck[k].z = fmaf(cf, v.z, acck[k].z);
          acck[k].w = fmaf(cf, v.w, acck[k].w);
        }
      }
    }
#pragma unroll
    for (int k = 0; k < KP; k++){
      float4 o = acck[k];
      uint2 hv = make_uint2(f2h2(o.x, o.y), f2h2(o.z, o.w));
      *(uint2*)(smem + F_T1 + (uint32_t)((k*CC + c)*272 + w4*2)) = hv;
    }
  }

  cp_wait<0>();
  __syncthreads();

  // ---- phase B: HMMA fp16 single-product, 10 warps = 5m x 2n,
  //      warp tile 16m x 64w
  int mi = wid >> 1, ni = wid & 1;
  float acc[8][4];
#pragma unroll
  for (int nt = 0; nt < 8; nt++)
#pragma unroll
    for (int j = 0; j < 4; j++) acc[nt][j] = 0.f;

  uint32_t arow = (uint32_t)(mi*16 + (lane & 15));
  uint32_t alh  = (uint32_t)((lane >> 4) * 16);
  uint32_t brow16 = (uint32_t)(lane & 15);
  uint32_t blh  = (uint32_t)((lane >> 4) * 16);

#pragma unroll
  for (int kt = 0; kt < 5; kt++){
    uint32_t a_h[4];
    ldsm4(a_h, sb + F_CH + arow*176 + (uint32_t)kt*32 + alh);
#pragma unroll
    for (int g = 0; g < 4; g++){
      uint32_t b_f[4];
      uint32_t baddr = ((uint32_t)kt*16 + brow16)*272 + (uint32_t)(ni*128 + g*32) + blh;
      ldsm4t(b_f, sb + F_T1 + baddr);
      mma16816h(acc[g*2+0], a_h, b_f + 0);
      mma16816h(acc[g*2+1], a_h, b_f + 2);
    }
  }

  __syncthreads();   // t1 tile fully consumed; s overlay becomes legal

  // accumulators -> s tile [80][136] fp16 (stride 272 B, conflict-free)
  {
    int gid = lane >> 2, qc = (lane & 3)*2;
    int row = mi*16 + gid;
#pragma unroll
    for (int nt = 0; nt < 8; nt++){
      int col = ni*64 + nt*8 + qc;
      *(uint32_t*)(smem + F_SD + row*272 + col*2)     = f2h2(acc[nt][0], acc[nt][1]);
      *(uint32_t*)(smem + F_SD + (row+8)*272 + col*2) = f2h2(acc[nt][2], acc[nt][3]);
    }
  }
  __syncthreads();

  // ---- phase C: stage-3 stencil; warps 0-3 (one per SMSP), 4 u each.
  // s read as fp16 (LDS.64), band2T coef vectors straight from global (L1-hot).
  // Lanes own q = lane*4..lane*4+3; edge neighbors via shfl of the packed
  // fp16x2 pair (lanes 0/31 garbage x exactly-zero band coefficients).
  if (wid < 4){
    int q4 = lane*4;
    float o[4][4];
#pragma unroll
    for (int s2 = 0; s2 < 4; s2++)
#pragma unroll
      for (int j = 0; j < 4; j++) o[s2][j] = 0.f;

#pragma unroll
    for (int l = 0; l < KP; l++){
      const int nd = 2*l + 1;
      float4 cj[9];
#pragma unroll
      for (int dd = 0; dd < nd; dd++)
        cj[dd] = __ldg((const float4*)(g_band2T + (l*l + dd)*LL + q4));
#pragma unroll
      for (int s2 = 0; s2 < 4; s2++){
        int u = wid + s2*4;
        uint2 v = *(const uint2*)(smem + F_SD + (l*UU + u)*272 + q4*2);
        uint2 vm, vp;
        vm.x = __shfl_up_sync(0xffffffffu, v.x, 1);
        vm.y = __shfl_up_sync(0xffffffffu, v.y, 1);
        vp.x = __shfl_down_sync(0xffffffffu, v.x, 1);
        vp.y = __shfl_down_sync(0xffffffffu, v.y, 1);
        float2 fm0 = __half22float2(*(const __half2*)&vm.x);
        float2 fm1 = __half22float2(*(const __half2*)&vm.y);
        float2 fv0 = __half22float2(*(const __half2*)&v.x);
        float2 fv1 = __half22float2(*(const __half2*)&v.y);
        float2 fp0 = __half22float2(*(const __half2*)&vp.x);
        float2 fp1 = __half22float2(*(const __half2*)&vp.y);
        float w[12] = {fm0.x, fm0.y, fm1.x, fm1.y,
                       fv0.x, fv0.y, fv1.x, fv1.y,
                       fp0.x, fp0.y, fp1.x, fp1.y};
#pragma unroll
        for (int j = 0; j < 4; j++)
#pragma unroll
          for (int dd = 0; dd < nd; dd++)
            o[s2][j] = fmaf(((const float*)&cj[dd])[j], w[4 + j + dd - l], o[s2][j]);
      }
    }
#pragma unroll
    for (int s2 = 0; s2 < 4; s2++){
      int u = wid + s2*4;
      *(float4*)(out + ((size_t)(b*UU + u)*LL + p)*LL + q4) =
          make_float4(o[s2][0], o[s2][1], o[s2][2], o[s2][3]);
    }
  }
}

// ============================================================================
extern "C" void kernel_launch(void* const* d_in, const int* in_sizes, int n_in,
                              void* d_out, int out_size)
{
  const float* x = nullptr;
  const float* coefs = nullptr;
  const float* cheb1 = nullptr;
  const float* cheb2 = nullptr;
  for (int i = 0; i < n_in; i++){
    int sz = in_sizes[i];
    const float* p = (const float*)d_in[i];
    if (sz == BB*CC*PW)            x = p;
    else if (sz == KP*KP*CC*UU)    coefs = p;
    else if (sz == KP*PW){ if (!cheb1) cheb1 = p; else cheb2 = p; }
  }
  if (!cheb2) cheb2 = cheb1;
  float* out = (float*)d_out;

  cudaFuncSetAttribute(fused_all, cudaFuncAttributeMaxDynamicSharedMemorySize, F_SMEM);

  prep_tabs<<<64, 128>>>(cheb1, cheb2, coefs);
  fused_all<<<dim3(LL, BB), 320, F_SMEM>>>(x, out);
}

// round 15
// speedup vs baseline: 1.2836x; 1.2836x over previous
#include <cuda_runtime.h>
#include <cuda_fp16.h>
#include <cstdint>

#define BB 32
#define CC 16
#define UU 16
#define LL 128
#define PW (LL*LL)
#define KP 5
#define MKC 80
#define MLU 80

// C is scaled by 4096 (exact power of 2); band2T pre-divided by 4096.
#define CSCALE 4096.0f

// ------------------------------- scratch ------------------------------------
__device__ float  g_band1[LL*25];      // packed band of cheb1 [p][25]
__device__ float  g_band2T[25*LL];     // packed band of cheb2 /CSCALE, [j][q]
__device__ __half g_Chi[MLU*88];       // coef*CSCALE fp16 [m][kk pad 88]

// --------------------------- helpers ------------------------------
__device__ __forceinline__ void cp16(uint32_t dst, const void* src){
  asm volatile("cp.async.cg.shared.global [%0], [%1], 16;" :: "r"(dst), "l"(src));
}
__device__ __forceinline__ void cp_commit(){ asm volatile("cp.async.commit_group;"); }
template<int N> __device__ __forceinline__ void cp_wait(){
  asm volatile("cp.async.wait_group %0;" :: "n"(N));
}
__device__ __forceinline__ uint32_t smem_u32(const void* p){
  return (uint32_t)__cvta_generic_to_shared(p);
}
// pack two floats to fp16x2 (lo arg in low half)
__device__ __forceinline__ uint32_t f2h2(float lo, float hi){
  uint32_t r;
  asm("cvt.rn.f16x2.f32 %0, %1, %2;" : "=r"(r) : "f"(hi), "f"(lo));
  return r;
}
// m16n8k16 fp16 MMA, fp32 accumulate
__device__ __forceinline__ void mma16816h(float* d, const uint32_t* a, const uint32_t* b){
  asm volatile("mma.sync.aligned.m16n8k16.row.col.f32.f16.f16.f32 "
    "{%0,%1,%2,%3}, {%4,%5,%6,%7}, {%8,%9}, {%0,%1,%2,%3};"
    : "+f"(d[0]),"+f"(d[1]),"+f"(d[2]),"+f"(d[3])
    : "r"(a[0]),"r"(a[1]),"r"(a[2]),"r"(a[3]), "r"(b[0]),"r"(b[1]));
}
__device__ __forceinline__ void ldsm4(uint32_t* r, uint32_t addr){
  asm volatile("ldmatrix.sync.aligned.m8n8.x4.shared.b16 {%0,%1,%2,%3}, [%4];"
    : "=r"(r[0]),"=r"(r[1]),"=r"(r[2]),"=r"(r[3]) : "r"(addr));
}
__device__ __forceinline__ void ldsm4t(uint32_t* r, uint32_t addr){
  asm volatile("ldmatrix.sync.aligned.m8n8.x4.trans.shared.b16 {%0,%1,%2,%3}, [%4];"
    : "=r"(r[0]),"=r"(r[1]),"=r"(r[2]),"=r"(r[3]) : "r"(addr));
}

// ============================================================================
// Prep: band tables (T_k has bandwidth k — exact structural zeros).
// band1[p][k*k+k+d] = c1[k][p+d][p];  band2T[(k*k+k+d)][q] = c2[k][q+d][q]/CSCALE
// C[m=(l,u)][kk=(k1,c)]*CSCALE -> fp16, kk padded to 88.
// ============================================================================
__global__ void prep_tabs(const float* __restrict__ c1, const float* __restrict__ c2,
                          const float* __restrict__ coefs){
  int gt = blockIdx.x*128 + threadIdx.x;   // 64 x 128 = 8192
  if (gt < LL){
    int t = gt;
#pragma unroll
    for (int k = 0; k < KP; k++)
      for (int d = -k; d <= k; d++){
        int h = t + d;
        bool ok = (h >= 0 && h < LL);
        g_band1[t*25 + k*k + k + d] = ok ? c1[(k*LL + h)*LL + t] : 0.f;
        g_band2T[(k*k + k + d)*LL + t] = ok ? (c2[(k*LL + h)*LL + t] * (1.0f/CSCALE)) : 0.f;
      }
  }
  for (int i = gt; i < MLU*88; i += 8192){
    int m = i / 88, kk = i % 88;
    float v = 0.f;
    if (kk < MKC){
      int l = m >> 4, u = m & 15, k1 = kk >> 4, c = kk & 15;
      v = coefs[((k1*KP + l)*CC + c)*UU + u] * CSCALE;
    }
    g_Chi[i] = __float2half_rn(v);
  }
}

// ============================================================================
// Fully fused kernel, one block per (b, p):
//   phase A (fp32 stencil, d-major): t1[kk][w] -> single fp16 ldsm tile
//   phase B (HMMA fp16): s[m][w] = Chi[m][kk] * t1f16[kk][w]
//   phase C (shfl-windowed f32 stencil, 4 warps x 4u): out = sum_{l,d} band2T*s
// SMEM layout (55104 B, occ 3):
//   band2T[25][128]f (dedicated, loaded in prologue) | t1[80][136]h |
//   Chi[80][88]h | band1[32]f
//   phase C overlay: s[80][132]f32 at F_SD over dead t1/C/band1 regions.
// ============================================================================
#define F_B2   0                 // band2T, 12800 B — live whole kernel
#define F_T1   12800             // t1 fp16 tile, 21760 B
#define F_CH   34560             // C fp16 tile, 14080 B
#define F_BND1 48640             // band1, 128 B
#define F_SMEM 55104             // bytes (s overlay high-water: 12816+42240=55056)
#define F_SD   12816             // s tile [80][132] f32, overlays t1/C/band1

__global__ __launch_bounds__(320,3) void fused_all(const float* __restrict__ x,
                                                   float* __restrict__ out){
  extern __shared__ char smem[];
  uint32_t sb = smem_u32(smem);
  int tid = threadIdx.x, wid = tid >> 5, lane = tid & 31;
  int p = blockIdx.x, b = blockIdx.y;

  // ---- prologue async loads: C tile (880 chunks) + band2T (800 chunks) ----
  for (int i = tid; i < 880; i += 320){
    int r = i / 11, ch = i % 11;
    cp16(sb + F_CH + r*176 + ch*16, g_Chi + r*88 + ch*8);
  }
  for (int i = tid; i < 800; i += 320)
    cp16(sb + F_B2 + i*16, g_band2T + i*4);
  cp_commit();

  // ---- band1[p] into smem (broadcast table for phase A) ----
  float* bnd_s = (float*)(smem + F_BND1);
  if (tid < 25) bnd_s[tid] = g_band1[p*25 + tid];
  __syncthreads();

  // ---- phase A: stage-1 stencil, d-major; output single fp16 tile ----
  for (int i = tid; i < 512; i += 320){
    int c  = i >> 5;
    int w4 = (i & 31) << 2;
    const float* xs = x + (size_t)(b*CC + c)*PW + w4;
    float4 acck[5];
#pragma unroll
    for (int k = 0; k < KP; k++) acck[k] = make_float4(0.f,0.f,0.f,0.f);
#pragma unroll
    for (int d = -4; d <= 4; d++){
      int h = p + d;
      h = h < 0 ? 0 : (h > 127 ? 127 : h);
      float4 v = *(const float4*)(xs + h*LL);
      int ad = d < 0 ? -d : d;
#pragma unroll
      for (int k = 0; k < KP; k++){
        if (k >= ad){
          float cf = bnd_s[k*k + k + d];
          acck[k].x = fmaf(cf, v.x, acck[k].x);
          acck[k].y = fmaf(cf, v.y, acck[k].y);
          acck[k].z = fmaf(cf, v.z, acck[k].z);
          acck[k].w = fmaf(cf, v.w, acck[k].w);
        }
      }
    }
#pragma unroll
    for (int k = 0; k < KP; k++){
      float4 o = acck[k];
      uint2 hv = make_uint2(f2h2(o.x, o.y), f2h2(o.z, o.w));
      *(uint2*)(smem + F_T1 + (uint32_t)((k*CC + c)*272 + w4*2)) = hv;
    }
  }

  cp_wait<0>();
  __syncthreads();

  // ---- phase B: HMMA fp16 single-product, 10 warps = 5m x 2n,
  //      warp tile 16m x 64w
  int mi = wid >> 1, ni = wid & 1;
  float acc[8][4];
#pragma unroll
  for (int nt = 0; nt < 8; nt++)
#pragma unroll
    for (int j = 0; j < 4; j++) acc[nt][j] = 0.f;

  uint32_t arow = (uint32_t)(mi*16 + (lane & 15));
  uint32_t alh  = (uint32_t)((lane >> 4) * 16);
  uint32_t brow16 = (uint32_t)(lane & 15);
  uint32_t blh  = (uint32_t)((lane >> 4) * 16);

#pragma unroll
  for (int kt = 0; kt < 5; kt++){
    uint32_t a_h[4];
    ldsm4(a_h, sb + F_CH + arow*176 + (uint32_t)kt*32 + alh);
#pragma unroll
    for (int g = 0; g < 4; g++){
      uint32_t b_f[4];
      uint32_t baddr = ((uint32_t)kt*16 + brow16)*272 + (uint32_t)(ni*128 + g*32) + blh;
      ldsm4t(b_f, sb + F_T1 + baddr);
      mma16816h(acc[g*2+0], a_h, b_f + 0);
      mma16816h(acc[g*2+1], a_h, b_f + 2);
    }
  }

  __syncthreads();   // t1 + C tiles fully consumed; s overlay becomes legal

  // accumulators -> s tile [80][132] f32 (float2 stores)
  {
    float* sT = (float*)(smem + F_SD);
    int gid = lane >> 2, qc = (lane & 3)*2;
    int row = mi*16 + gid;
#pragma unroll
    for (int nt = 0; nt < 8; nt++){
      int col = ni*64 + nt*8 + qc;
      *(float2*)(sT + row*132 + col)     = make_float2(acc[nt][0], acc[nt][1]);
      *(float2*)(sT + (row+8)*132 + col) = make_float2(acc[nt][2], acc[nt][3]);
    }
  }
  __syncthreads();

  // ---- phase C: stage-3 stencil, shfl-windowed; warps 0-3 (one per SMSP),
  // each warp handles 4 u values (u = wid + 4*s2); coef vectors load once per
  // warp and serve 4 outputs. Lanes own q = lane*4..lane*4+3; edge neighbors
  // via shfl (lanes 0/31 self-values x exactly-zero band coefficients).
  if (wid < 4){
    const float* bT = (const float*)(smem + F_B2);    // [25][128]
    const float* sT = (const float*)(smem + F_SD);    // [80][132]
    int q4 = lane*4;
    float o[4][4];
#pragma unroll
    for (int s2 = 0; s2 < 4; s2++)
#pragma unroll
      for (int j = 0; j < 4; j++) o[s2][j] = 0.f;

#pragma unroll
    for (int l = 0; l < KP; l++){
      const int nd = 2*l + 1;
      float4 cj[9];
#pragma unroll
      for (int dd = 0; dd < nd; dd++)
        cj[dd] = *(const float4*)(bT + (l*l + dd)*LL + q4);
#pragma unroll
      for (int s2 = 0; s2 < 4; s2++){
        int u = wid + s2*4;
        const float* srow = sT + (l*UU + u)*132;
        float4 v = *(const float4*)(srow + q4);
        float4 wm, wp;
        wm.x = __shfl_up_sync(0xffffffffu, v.x, 1);
        wm.y = __shfl_up_sync(0xffffffffu, v.y, 1);
        wm.z = __shfl_up_sync(0xffffffffu, v.z, 1);
        wm.w = __shfl_up_sync(0xffffffffu, v.w, 1);
        wp.x = __shfl_down_sync(0xffffffffu, v.x, 1);
        wp.y = __shfl_down_sync(0xffffffffu, v.y, 1);
        wp.z = __shfl_down_sync(0xffffffffu, v.z, 1);
        wp.w = __shfl_down_sync(0xffffffffu, v.w, 1);
        float w[12] = {wm.x,wm.y,wm.z,wm.w, v.x,v.y,v.z,v.w, wp.x,wp.y,wp.z,wp.w};
#pragma unroll
        for (int j = 0; j < 4; j++)
#pragma unroll
          for (int dd = 0; dd < nd; dd++)
            o[s2][j] = fmaf(((const float*)&cj[dd])[j], w[4 + j + dd - l], o[s2][j]);
      }
    }
#pragma unroll
    for (int s2 = 0; s2 < 4; s2++){
      int u = wid + s2*4;
      *(float4*)(out + ((size_t)(b*UU + u)*LL + p)*LL + q4) =
          make_float4(o[s2][0], o[s2][1], o[s2][2], o[s2][3]);
    }
  }
}

// ============================================================================
extern "C" void kernel_launch(void* const* d_in, const int* in_sizes, int n_in,
                              void* d_out, int out_size)
{
  const float* x = nullptr;
  const float* coefs = nullptr;
  const float* cheb1 = nullptr;
  const float* cheb2 = nullptr;
  for (int i = 0; i < n_in; i++){
    int sz = in_sizes[i];
    const float* p = (const float*)d_in[i];
    if (sz == BB*CC*PW)            x = p;
    else if (sz == KP*KP*CC*UU)    coefs = p;
    else if (sz == KP*PW){ if (!cheb1) cheb1 = p; else cheb2 = p; }
  }
  if (!cheb2) cheb2 = cheb1;
  float* out = (float*)d_out;

  cudaFuncSetAttribute(fused_all, cudaFuncAttributeMaxDynamicSharedMemorySize, F_SMEM);

  prep_tabs<<<64, 128>>>(cheb1, cheb2, coefs);
  fused_all<<<dim3(LL, BB), 320, F_SMEM>>>(x, out);
}